// round 7
// baseline (speedup 1.0000x reference)
#include <cuda_runtime.h>

#define NN 100000
#define NE 1600000
#define NG 64
#define NC 10

// ---------------- static scratch (no allocations allowed) ----------------
__device__ float g_H[(size_t)NN * 128];   // current node features
__device__ float g_T[(size_t)NN * 128];   // transformed features (h @ W)
__device__ int   g_deg[NN];
__device__ float g_dinv[NN];
__device__ float g_psum[NG * 32];
__device__ float g_pcnt[NG];
__device__ int   g_ei64;                  // 1 if edge_index is int64
__device__ int   g_b64;                   // 1 if batch is int64

// ---------------- dtype detection (int64 vs int32 indices) ----------------
// If the array is int64 (values < 2^31, nonneg), every odd 32-bit word is 0.
// If int32, odd words are node-ids / graph-ids, whose OR is nonzero w.p. ~1.
__global__ void k_detect(const unsigned int* __restrict__ ei_w,
                         const unsigned int* __restrict__ b_w) {
    __shared__ unsigned sa, sb;
    int tid = threadIdx.x;
    if (tid == 0) { sa = 0u; sb = 0u; }
    __syncthreads();
    unsigned a = 0u, b = 0u;
    // edge words: safe to read first 4096 32-bit words under either dtype
    for (int i = tid; i < 2048; i += 256) a |= ei_w[2 * i + 1];
    // batch words: only first 100000 words are guaranteed; sample odd words
    for (int i = tid; i < 2048; i += 256) {
        int k = i * 24;                 // k < 49152  -> word index < 100000
        b |= b_w[2 * k + 1];
    }
    atomicOr(&sa, a); atomicOr(&sb, b);
    __syncthreads();
    if (tid == 0) { g_ei64 = (sa == 0u) ? 1 : 0; g_b64 = (sb == 0u) ? 1 : 0; }
}

// ---------------- degree / normalization ----------------
__global__ void k_init() {
    int i = blockIdx.x * blockDim.x + threadIdx.x;
    if (i < NN)      g_deg[i] = 1;         // self loop
    if (i < NG * 32) g_psum[i] = 0.f;
    if (i < NG)      g_pcnt[i] = 0.f;
}

__global__ void k_deg_count(const void* __restrict__ ei) {
    const int is64 = g_ei64;
    const long long* e64 = (const long long*)ei;
    const int*       e32 = (const int*)ei;
    int t = blockIdx.x * blockDim.x + threadIdx.x;
    int stride = gridDim.x * blockDim.x;
    for (int e = t; e < NE; e += stride) {
        int d = is64 ? (int)e64[(size_t)NE + e] : e32[NE + e];
        atomicAdd(&g_deg[d], 1);
    }
}

__global__ void k_dinv() {
    int i = blockIdx.x * blockDim.x + threadIdx.x;
    if (i < NN) g_dinv[i] = rsqrtf((float)g_deg[i]);
}

// ---------------- SGEMM: C[M,FOUT] = relu?(A[M,K]) @ W[K,FOUT] ----------------
// BM=128 rows per block, full FOUT per block, 256 threads, 8 x (FOUT/16) micro-tile.
template <int K, int FOUT, bool RELU>
__global__ void __launch_bounds__(256) k_gemm(const float* __restrict__ A,
                                              const float* __restrict__ W,
                                              float* __restrict__ C) {
    constexpr int BM = 128, BK = 16;
    constexpr int TM = 8, TN = FOUT / 16;
    __shared__ float As[BK][BM + 4];   // A tile, transposed
    __shared__ float Bs[BK][FOUT];
    const int tid = threadIdx.x;
    const int tx = tid % 16, ty = tid / 16;
    const int row0 = blockIdx.x * BM;

    float acc[TM][TN];
#pragma unroll
    for (int m = 0; m < TM; m++)
#pragma unroll
        for (int n = 0; n < TN; n++) acc[m][n] = 0.f;

    for (int k0 = 0; k0 < K; k0 += BK) {
        // load A tile (BM x BK), float4, relu on read
#pragma unroll
        for (int i = tid; i < BM * (BK / 4); i += 256) {
            int r = i / (BK / 4);
            int c = i % (BK / 4);
            int gr = row0 + r;
            float4 v = make_float4(0.f, 0.f, 0.f, 0.f);
            if (gr < NN) v = *(const float4*)(A + (size_t)gr * K + k0 + c * 4);
            if (RELU) {
                v.x = fmaxf(v.x, 0.f); v.y = fmaxf(v.y, 0.f);
                v.z = fmaxf(v.z, 0.f); v.w = fmaxf(v.w, 0.f);
            }
            As[c * 4 + 0][r] = v.x; As[c * 4 + 1][r] = v.y;
            As[c * 4 + 2][r] = v.z; As[c * 4 + 3][r] = v.w;
        }
        // load W tile (BK x FOUT)
#pragma unroll
        for (int i = tid; i < BK * (FOUT / 4); i += 256) {
            int r = i / (FOUT / 4);
            int c = i % (FOUT / 4);
            *(float4*)&Bs[r][c * 4] =
                *(const float4*)(W + (size_t)(k0 + r) * FOUT + c * 4);
        }
        __syncthreads();
#pragma unroll
        for (int k = 0; k < BK; k++) {
            float ra[TM], rb[TN];
#pragma unroll
            for (int m = 0; m < TM; m++) ra[m] = As[k][ty * TM + m];
#pragma unroll
            for (int n = 0; n < TN; n++) rb[n] = Bs[k][tx * TN + n];
#pragma unroll
            for (int m = 0; m < TM; m++)
#pragma unroll
                for (int n = 0; n < TN; n++)
                    acc[m][n] = fmaf(ra[m], rb[n], acc[m][n]);
        }
        __syncthreads();
    }
#pragma unroll
    for (int m = 0; m < TM; m++) {
        int gr = row0 + ty * TM + m;
        if (gr < NN) {
            if constexpr (TN % 4 == 0) {
#pragma unroll
                for (int n = 0; n < TN; n += 4) {
                    float4 v = make_float4(acc[m][n], acc[m][n + 1],
                                           acc[m][n + 2], acc[m][n + 3]);
                    *(float4*)(C + (size_t)gr * FOUT + tx * TN + n) = v;
                }
            } else {
#pragma unroll
                for (int n = 0; n < TN; n += 2) {
                    float2 v = make_float2(acc[m][n], acc[m][n + 1]);
                    *(float2*)(C + (size_t)gr * FOUT + tx * TN + n) = v;
                }
            }
        }
    }
}

// ---------------- aggregation init: H = b + T * dinv^2 (self loop) ----------------
template <int F>
__global__ void k_agg_init(const float* __restrict__ T, const float* __restrict__ b,
                           float* __restrict__ H) {
    constexpr int L = F / 4;
    long i = (long)blockIdx.x * blockDim.x + threadIdx.x;
    long total = (long)NN * L;
    if (i >= total) return;
    int node = (int)(i / L);
    int c = (int)(i % L);
    float di = g_dinv[node];
    float s = di * di;
    float4 t = ((const float4*)T)[i];
    float4 bv = ((const float4*)b)[c];
    float4 o;
    o.x = fmaf(t.x, s, bv.x); o.y = fmaf(t.y, s, bv.y);
    o.z = fmaf(t.z, s, bv.z); o.w = fmaf(t.w, s, bv.w);
    ((float4*)H)[i] = o;
}

// ---------------- edge scatter: H[dst] += T[src] * norm ----------------
__device__ __forceinline__ void red_add_v4(float* p, float4 v) {
    asm volatile("red.global.add.v4.f32 [%0], {%1, %2, %3, %4};"
                 :: "l"(p), "f"(v.x), "f"(v.y), "f"(v.z), "f"(v.w) : "memory");
}

template <int F>
__global__ void k_scatter(const void* __restrict__ ei,
                          const float* __restrict__ T,
                          float* __restrict__ H) {
    constexpr int L = F / 4;                // lanes per edge (power of 2)
    const int is64 = g_ei64;
    const long long* e64 = (const long long*)ei;
    const int*       e32 = (const int*)ei;
    int t = blockIdx.x * blockDim.x + threadIdx.x;
    int lane = t % L;
    int e0 = t / L;
    int estride = (gridDim.x * blockDim.x) / L;
    for (int e = e0; e < NE; e += estride) {
        int s, d;
        if (is64) { s = (int)e64[e]; d = (int)e64[(size_t)NE + e]; }
        else      { s = e32[e];      d = e32[NE + e]; }
        float nrm = g_dinv[s] * g_dinv[d];
        float4 v = *(const float4*)(T + (size_t)s * F + lane * 4);
        v.x *= nrm; v.y *= nrm; v.z *= nrm; v.w *= nrm;
        red_add_v4(H + (size_t)d * F + lane * 4, v);
    }
}

// ---------------- mean pool (with relu) ----------------
__global__ void k_pool(const void* __restrict__ batch, const float* __restrict__ H) {
    const int is64 = g_b64;
    const long long* b64 = (const long long*)batch;
    const int*       b32 = (const int*)batch;
    int t = blockIdx.x * blockDim.x + threadIdx.x;
    int lane = t & 31;
    int n0 = t >> 5;
    int nstride = (gridDim.x * blockDim.x) >> 5;
    for (int n = n0; n < NN; n += nstride) {
        int g = is64 ? (int)b64[n] : b32[n];
        float v = fmaxf(H[(size_t)n * 32 + lane], 0.f);
        atomicAdd(&g_psum[g * 32 + lane], v);
        if (lane == 0) atomicAdd(&g_pcnt[g], 1.f);
    }
}

// ---------------- final FC: out = (psum/cnt) @ Wfc + bfc ----------------
__global__ void k_fc(const float* __restrict__ Wfc, const float* __restrict__ bfc,
                     float* __restrict__ out) {
    int t = threadIdx.x;
    if (t >= NG * NC) return;
    int g = t / NC, c = t % NC;
    float inv = 1.f / fmaxf(g_pcnt[g], 1.f);
    float acc = bfc[c];
#pragma unroll
    for (int k = 0; k < 32; k++)
        acc = fmaf(g_psum[g * 32 + k] * inv, Wfc[k * NC + c], acc);
    out[t] = acc;
}

// ---------------- host launcher ----------------
extern "C" void kernel_launch(void* const* d_in, const int* in_sizes, int n_in,
                              void* d_out, int out_size) {
    const float* x    = (const float*)d_in[0];
    const void*  ei   = d_in[1];
    const void*  batch= d_in[2];
    const float* W1 = (const float*)d_in[3];  const float* b1 = (const float*)d_in[4];
    const float* W2 = (const float*)d_in[5];  const float* b2 = (const float*)d_in[6];
    const float* W3 = (const float*)d_in[7];  const float* b3 = (const float*)d_in[8];
    const float* W4 = (const float*)d_in[9];  const float* b4 = (const float*)d_in[10];
    const float* W5 = (const float*)d_in[11]; const float* b5 = (const float*)d_in[12];
    const float* Wfc= (const float*)d_in[13]; const float* bfc= (const float*)d_in[14];
    float* out = (float*)d_out;

    float *H, *T;
    cudaGetSymbolAddress((void**)&H, g_H);
    cudaGetSymbolAddress((void**)&T, g_T);

    const int GB = (NN + 127) / 128;   // gemm blocks

    k_detect<<<1, 256>>>((const unsigned int*)ei, (const unsigned int*)batch);
    k_init<<<(NN + 255) / 256, 256>>>();
    k_deg_count<<<2048, 256>>>(ei);
    k_dinv<<<(NN + 255) / 256, 256>>>();

    // Layer 1: 128 -> 128 (no relu on input x)
    k_gemm<128, 128, false><<<GB, 256>>>(x, W1, T);
    k_agg_init<128><<<(NN * 32 + 255) / 256, 256>>>(T, b1, H);
    k_scatter<128><<<2048, 256>>>(ei, T, H);

    // Layer 2: 128 -> 128
    k_gemm<128, 128, true><<<GB, 256>>>(H, W2, T);
    k_agg_init<128><<<(NN * 32 + 255) / 256, 256>>>(T, b2, H);
    k_scatter<128><<<2048, 256>>>(ei, T, H);

    // Layer 3: 128 -> 128
    k_gemm<128, 128, true><<<GB, 256>>>(H, W3, T);
    k_agg_init<128><<<(NN * 32 + 255) / 256, 256>>>(T, b3, H);
    k_scatter<128><<<2048, 256>>>(ei, T, H);

    // Layer 4: 128 -> 64
    k_gemm<128, 64, true><<<GB, 256>>>(H, W4, T);
    k_agg_init<64><<<(NN * 16 + 255) / 256, 256>>>(T, b4, H);
    k_scatter<64><<<2048, 256>>>(ei, T, H);

    // Layer 5: 64 -> 32
    k_gemm<64, 32, true><<<GB, 256>>>(H, W5, T);
    k_agg_init<32><<<(NN * 8 + 255) / 256, 256>>>(T, b5, H);
    k_scatter<32><<<2048, 256>>>(ei, T, H);

    // Pool + FC
    k_pool<<<1024, 256>>>(batch, H);
    k_fc<<<1, 640>>>(Wfc, bfc, out);
}

// round 8
// speedup vs baseline: 1.0049x; 1.0049x over previous
#include <cuda_runtime.h>

#define NN 100000
#define NE 1600000
#define NG 64
#define NC 10

// ---------------- static scratch (no allocations allowed) ----------------
__device__ float g_H[(size_t)NN * 128];   // current node features
__device__ float g_T[(size_t)NN * 128];   // transformed features (h @ W)
__device__ int   g_deg[NN];
__device__ float g_dinv[NN];
__device__ float g_psum[NG * 32];
__device__ float g_pcnt[NG];
__device__ int   g_ei64;                  // 1 if edge_index is int64
__device__ int   g_b64;                   // 1 if batch is int64

// ---------------- dtype detection (int64 vs int32 indices) ----------------
// If the array is int64 (values < 2^31, nonneg), every odd 32-bit word is 0.
// If int32, odd words are node-ids / graph-ids, whose OR is nonzero w.p. ~1.
__global__ void k_detect(const unsigned int* __restrict__ ei_w,
                         const unsigned int* __restrict__ b_w) {
    __shared__ unsigned sa, sb;
    int tid = threadIdx.x;
    if (tid == 0) { sa = 0u; sb = 0u; }
    __syncthreads();
    unsigned a = 0u, b = 0u;
    // edge words: safe to read first 4096 32-bit words under either dtype
    for (int i = tid; i < 2048; i += 256) a |= ei_w[2 * i + 1];
    // batch words: only first 100000 words are guaranteed; sample odd words
    for (int i = tid; i < 2048; i += 256) {
        int k = i * 24;                 // k < 49152  -> word index < 100000
        b |= b_w[2 * k + 1];
    }
    atomicOr(&sa, a); atomicOr(&sb, b);
    __syncthreads();
    if (tid == 0) { g_ei64 = (sa == 0u) ? 1 : 0; g_b64 = (sb == 0u) ? 1 : 0; }
}

// ---------------- degree / normalization ----------------
__global__ void k_init() {
    int i = blockIdx.x * blockDim.x + threadIdx.x;
    if (i < NN)      g_deg[i] = 1;         // self loop
    if (i < NG * 32) g_psum[i] = 0.f;
    if (i < NG)      g_pcnt[i] = 0.f;
}

__global__ void k_deg_count(const void* __restrict__ ei) {
    const int is64 = g_ei64;
    const long long* e64 = (const long long*)ei;
    const int*       e32 = (const int*)ei;
    int t = blockIdx.x * blockDim.x + threadIdx.x;
    int stride = gridDim.x * blockDim.x;
    for (int e = t; e < NE; e += stride) {
        int d = is64 ? (int)e64[(size_t)NE + e] : e32[NE + e];
        atomicAdd(&g_deg[d], 1);
    }
}

__global__ void k_dinv() {
    int i = blockIdx.x * blockDim.x + threadIdx.x;
    if (i < NN) g_dinv[i] = rsqrtf((float)g_deg[i]);
}

// ---------------- SGEMM: C[M,FOUT] = relu?(A[M,K]) @ W[K,FOUT] ----------------
// BM=128 rows per block, full FOUT per block, 256 threads, 8 x (FOUT/16) micro-tile.
template <int K, int FOUT, bool RELU>
__global__ void __launch_bounds__(256) k_gemm(const float* __restrict__ A,
                                              const float* __restrict__ W,
                                              float* __restrict__ C) {
    constexpr int BM = 128, BK = 16;
    constexpr int TM = 8, TN = FOUT / 16;
    __shared__ float As[BK][BM + 4];   // A tile, transposed
    __shared__ float Bs[BK][FOUT];
    const int tid = threadIdx.x;
    const int tx = tid % 16, ty = tid / 16;
    const int row0 = blockIdx.x * BM;

    float acc[TM][TN];
#pragma unroll
    for (int m = 0; m < TM; m++)
#pragma unroll
        for (int n = 0; n < TN; n++) acc[m][n] = 0.f;

    for (int k0 = 0; k0 < K; k0 += BK) {
        // load A tile (BM x BK), float4, relu on read
#pragma unroll
        for (int i = tid; i < BM * (BK / 4); i += 256) {
            int r = i / (BK / 4);
            int c = i % (BK / 4);
            int gr = row0 + r;
            float4 v = make_float4(0.f, 0.f, 0.f, 0.f);
            if (gr < NN) v = *(const float4*)(A + (size_t)gr * K + k0 + c * 4);
            if (RELU) {
                v.x = fmaxf(v.x, 0.f); v.y = fmaxf(v.y, 0.f);
                v.z = fmaxf(v.z, 0.f); v.w = fmaxf(v.w, 0.f);
            }
            As[c * 4 + 0][r] = v.x; As[c * 4 + 1][r] = v.y;
            As[c * 4 + 2][r] = v.z; As[c * 4 + 3][r] = v.w;
        }
        // load W tile (BK x FOUT)
#pragma unroll
        for (int i = tid; i < BK * (FOUT / 4); i += 256) {
            int r = i / (FOUT / 4);
            int c = i % (FOUT / 4);
            *(float4*)&Bs[r][c * 4] =
                *(const float4*)(W + (size_t)(k0 + r) * FOUT + c * 4);
        }
        __syncthreads();
#pragma unroll
        for (int k = 0; k < BK; k++) {
            float ra[TM], rb[TN];
#pragma unroll
            for (int m = 0; m < TM; m++) ra[m] = As[k][ty * TM + m];
#pragma unroll
            for (int n = 0; n < TN; n++) rb[n] = Bs[k][tx * TN + n];
#pragma unroll
            for (int m = 0; m < TM; m++)
#pragma unroll
                for (int n = 0; n < TN; n++)
                    acc[m][n] = fmaf(ra[m], rb[n], acc[m][n]);
        }
        __syncthreads();
    }
#pragma unroll
    for (int m = 0; m < TM; m++) {
        int gr = row0 + ty * TM + m;
        if (gr < NN) {
            if constexpr (TN % 4 == 0) {
#pragma unroll
                for (int n = 0; n < TN; n += 4) {
                    float4 v = make_float4(acc[m][n], acc[m][n + 1],
                                           acc[m][n + 2], acc[m][n + 3]);
                    *(float4*)(C + (size_t)gr * FOUT + tx * TN + n) = v;
                }
            } else {
#pragma unroll
                for (int n = 0; n < TN; n += 2) {
                    float2 v = make_float2(acc[m][n], acc[m][n + 1]);
                    *(float2*)(C + (size_t)gr * FOUT + tx * TN + n) = v;
                }
            }
        }
    }
}

// ---------------- aggregation init: H = b + T * dinv^2 (self loop) ----------------
template <int F>
__global__ void k_agg_init(const float* __restrict__ T, const float* __restrict__ b,
                           float* __restrict__ H) {
    constexpr int L = F / 4;
    long i = (long)blockIdx.x * blockDim.x + threadIdx.x;
    long total = (long)NN * L;
    if (i >= total) return;
    int node = (int)(i / L);
    int c = (int)(i % L);
    float di = g_dinv[node];
    float s = di * di;
    float4 t = ((const float4*)T)[i];
    float4 bv = ((const float4*)b)[c];
    float4 o;
    o.x = fmaf(t.x, s, bv.x); o.y = fmaf(t.y, s, bv.y);
    o.z = fmaf(t.z, s, bv.z); o.w = fmaf(t.w, s, bv.w);
    ((float4*)H)[i] = o;
}

// ---------------- edge scatter: H[dst] += T[src] * norm ----------------
__device__ __forceinline__ void red_add_v4(float* p, float4 v) {
    asm volatile("red.global.add.v4.f32 [%0], {%1, %2, %3, %4};"
                 :: "l"(p), "f"(v.x), "f"(v.y), "f"(v.z), "f"(v.w) : "memory");
}

template <int F>
__global__ void k_scatter(const void* __restrict__ ei,
                          const float* __restrict__ T,
                          float* __restrict__ H) {
    constexpr int L = F / 4;                // lanes per edge (power of 2)
    const int is64 = g_ei64;
    const long long* e64 = (const long long*)ei;
    const int*       e32 = (const int*)ei;
    int t = blockIdx.x * blockDim.x + threadIdx.x;
    int lane = t % L;
    int e0 = t / L;
    int estride = (gridDim.x * blockDim.x) / L;
    for (int e = e0; e < NE; e += estride) {
        int s, d;
        if (is64) { s = (int)e64[e]; d = (int)e64[(size_t)NE + e]; }
        else      { s = e32[e];      d = e32[NE + e]; }
        float nrm = g_dinv[s] * g_dinv[d];
        float4 v = *(const float4*)(T + (size_t)s * F + lane * 4);
        v.x *= nrm; v.y *= nrm; v.z *= nrm; v.w *= nrm;
        red_add_v4(H + (size_t)d * F + lane * 4, v);
    }
}

// ---------------- mean pool (with relu) ----------------
__global__ void k_pool(const void* __restrict__ batch, const float* __restrict__ H) {
    const int is64 = g_b64;
    const long long* b64 = (const long long*)batch;
    const int*       b32 = (const int*)batch;
    int t = blockIdx.x * blockDim.x + threadIdx.x;
    int lane = t & 31;
    int n0 = t >> 5;
    int nstride = (gridDim.x * blockDim.x) >> 5;
    for (int n = n0; n < NN; n += nstride) {
        int g = is64 ? (int)b64[n] : b32[n];
        float v = fmaxf(H[(size_t)n * 32 + lane], 0.f);
        atomicAdd(&g_psum[g * 32 + lane], v);
        if (lane == 0) atomicAdd(&g_pcnt[g], 1.f);
    }
}

// ---------------- final FC: out = (psum/cnt) @ Wfc + bfc ----------------
__global__ void k_fc(const float* __restrict__ Wfc, const float* __restrict__ bfc,
                     float* __restrict__ out) {
    int t = threadIdx.x;
    if (t >= NG * NC) return;
    int g = t / NC, c = t % NC;
    float inv = 1.f / fmaxf(g_pcnt[g], 1.f);
    float acc = bfc[c];
#pragma unroll
    for (int k = 0; k < 32; k++)
        acc = fmaf(g_psum[g * 32 + k] * inv, Wfc[k * NC + c], acc);
    out[t] = acc;
}

// ---------------- host launcher ----------------
extern "C" void kernel_launch(void* const* d_in, const int* in_sizes, int n_in,
                              void* d_out, int out_size) {
    const float* x    = (const float*)d_in[0];
    const void*  ei   = d_in[1];
    const void*  batch= d_in[2];
    const float* W1 = (const float*)d_in[3];  const float* b1 = (const float*)d_in[4];
    const float* W2 = (const float*)d_in[5];  const float* b2 = (const float*)d_in[6];
    const float* W3 = (const float*)d_in[7];  const float* b3 = (const float*)d_in[8];
    const float* W4 = (const float*)d_in[9];  const float* b4 = (const float*)d_in[10];
    const float* W5 = (const float*)d_in[11]; const float* b5 = (const float*)d_in[12];
    const float* Wfc= (const float*)d_in[13]; const float* bfc= (const float*)d_in[14];
    float* out = (float*)d_out;

    float *H, *T;
    cudaGetSymbolAddress((void**)&H, g_H);
    cudaGetSymbolAddress((void**)&T, g_T);

    const int GB = (NN + 127) / 128;   // gemm blocks

    k_detect<<<1, 256>>>((const unsigned int*)ei, (const unsigned int*)batch);
    k_init<<<(NN + 255) / 256, 256>>>();
    k_deg_count<<<2048, 256>>>(ei);
    k_dinv<<<(NN + 255) / 256, 256>>>();

    // Layer 1: 128 -> 128 (no relu on input x)
    k_gemm<128, 128, false><<<GB, 256>>>(x, W1, T);
    k_agg_init<128><<<(NN * 32 + 255) / 256, 256>>>(T, b1, H);
    k_scatter<128><<<2048, 256>>>(ei, T, H);

    // Layer 2: 128 -> 128
    k_gemm<128, 128, true><<<GB, 256>>>(H, W2, T);
    k_agg_init<128><<<(NN * 32 + 255) / 256, 256>>>(T, b2, H);
    k_scatter<128><<<2048, 256>>>(ei, T, H);

    // Layer 3: 128 -> 128
    k_gemm<128, 128, true><<<GB, 256>>>(H, W3, T);
    k_agg_init<128><<<(NN * 32 + 255) / 256, 256>>>(T, b3, H);
    k_scatter<128><<<2048, 256>>>(ei, T, H);

    // Layer 4: 128 -> 64
    k_gemm<128, 64, true><<<GB, 256>>>(H, W4, T);
    k_agg_init<64><<<(NN * 16 + 255) / 256, 256>>>(T, b4, H);
    k_scatter<64><<<2048, 256>>>(ei, T, H);

    // Layer 5: 64 -> 32
    k_gemm<64, 32, true><<<GB, 256>>>(H, W5, T);
    k_agg_init<32><<<(NN * 8 + 255) / 256, 256>>>(T, b5, H);
    k_scatter<32><<<2048, 256>>>(ei, T, H);

    // Pool + FC
    k_pool<<<1024, 256>>>(batch, H);
    k_fc<<<1, 640>>>(Wfc, bfc, out);
}